// round 2
// baseline (speedup 1.0000x reference)
#include <cuda_runtime.h>
#include <math.h>

#define NT 256
#define GZ (-9.80665f)

__device__ __constant__ int cLCOL[12] = {0,1,2,3,4,5,9,10,11,12,13,14};
__device__ __constant__ int cHCOL[12] = {3,4,5,9,10,11,15,16,17,18,19,20};

struct SM {
    float P[441], A[441], Pn[441];
    float Fc[108], L[108];
    float T9[189];
    float H[24];      // [2][12] compact
    float HP[42];     // [2][21]
    float K[42];      // [21][2]
    float KS[42];     // [21][2]
    float S[4];
    float r2[2], Rm2[2];
    float dx[21];
    float Rot[9], V[3], Pp[3], Bom[3], Bac[3], Rci[9], Tci[3];
    float Rotn[9], Vn[3], Pn3[3], Om[3];
    float in[2][9];   // t, u[6], mcov[2]
};

__device__ __forceinline__ void mm3(const float* A, const float* B, float* C) {
#pragma unroll
    for (int p = 0; p < 3; ++p)
#pragma unroll
        for (int q = 0; q < 3; ++q)
            C[p*3+q] = A[p*3+0]*B[0*3+q] + A[p*3+1]*B[1*3+q] + A[p*3+2]*B[2*3+q];
}

__device__ __forceinline__ float skew_elem(const float* w, int i, int j) {
    if (i == 0) return (j == 0) ? 0.f : ((j == 1) ? -w[2] : w[1]);
    if (i == 1) return (j == 0) ? w[2] : ((j == 1) ? 0.f : -w[0]);
    return (j == 0) ? -w[1] : ((j == 1) ? w[0] : 0.f);
}

// (skew(w) @ R)(rr, j)
__device__ __forceinline__ float skewrowdot(const float* w, const float* R, int rr, int j) {
    if (rr == 0) return -w[2]*R[3+j] + w[1]*R[6+j];
    if (rr == 1) return  w[2]*R[0+j] - w[0]*R[6+j];
    return -w[1]*R[0+j] + w[0]*R[3+j];
}

// skew((0,0,GZ))[rr][j]
__device__ __forceinline__ float SG(int rr, int j) {
    if (rr == 0 && j == 1) return -GZ;
    if (rr == 1 && j == 0) return  GZ;
    return 0.f;
}

__device__ __forceinline__ void so3exp_f(const float* phi, float* R) {
    float p0 = phi[0], p1 = phi[1], p2 = phi[2];
    float a2 = p0*p0 + p1*p1 + p2*p2;
    if (a2 < 1e-12f) {
        R[0] = 1.f; R[1] = -p2; R[2] = p1;
        R[3] = p2;  R[4] = 1.f; R[5] = -p0;
        R[6] = -p1; R[7] = p0;  R[8] = 1.f;
    } else {
        float a = sqrtf(a2), inva = 1.f / a;
        float ax = p0*inva, ay = p1*inva, az = p2*inva;
        float c = cosf(a), s = sinf(a), omc = 1.f - c;
        R[0] = c + omc*ax*ax;    R[1] = omc*ax*ay - s*az; R[2] = omc*ax*az + s*ay;
        R[3] = omc*ay*ax + s*az; R[4] = c + omc*ay*ay;    R[5] = omc*ay*az - s*ax;
        R[6] = omc*az*ax - s*ay; R[7] = omc*az*ay + s*ax; R[8] = c + omc*az*az;
    }
}

__device__ __forceinline__ void sen3exp_f(const float* xi, float* R, float* x0, float* x1) {
    float p0 = xi[0], p1 = xi[1], p2 = xi[2];
    float a2 = p0*p0 + p1*p1 + p2*p2;
    float J[9];
    if (a2 < 1e-12f) {
        R[0] = 1.f; R[1] = -p2; R[2] = p1;
        R[3] = p2;  R[4] = 1.f; R[5] = -p0;
        R[6] = -p1; R[7] = p0;  R[8] = 1.f;
        J[0] = 1.f;      J[1] = -0.5f*p2; J[2] = 0.5f*p1;
        J[3] = 0.5f*p2;  J[4] = 1.f;      J[5] = -0.5f*p0;
        J[6] = -0.5f*p1; J[7] = 0.5f*p0;  J[8] = 1.f;
    } else {
        float a = sqrtf(a2), inva = 1.f / a;
        float ax = p0*inva, ay = p1*inva, az = p2*inva;
        float c = cosf(a), s = sinf(a), omc = 1.f - c;
        R[0] = c + omc*ax*ax;    R[1] = omc*ax*ay - s*az; R[2] = omc*ax*az + s*ay;
        R[3] = omc*ay*ax + s*az; R[4] = c + omc*ay*ay;    R[5] = omc*ay*az - s*ax;
        R[6] = omc*az*ax - s*ay; R[7] = omc*az*ay + s*ax; R[8] = c + omc*az*az;
        float sa = s * inva, oms = 1.f - sa, omca = omc * inva;
        J[0] = sa + oms*ax*ax;      J[1] = oms*ax*ay - omca*az; J[2] = oms*ax*az + omca*ay;
        J[3] = oms*ay*ax + omca*az; J[4] = sa + oms*ay*ay;      J[5] = oms*ay*az - omca*ax;
        J[6] = oms*az*ax - omca*ay; J[7] = oms*az*ay + omca*ax; J[8] = sa + oms*az*az;
    }
#pragma unroll
    for (int q = 0; q < 3; ++q) {
        x0[q] = J[q*3+0]*xi[3] + J[q*3+1]*xi[4] + J[q*3+2]*xi[5];
        x1[q] = J[q*3+0]*xi[6] + J[q*3+1]*xi[7] + J[q*3+2]*xi[8];
    }
}

__device__ __forceinline__ void normrot(float* X) {
    for (int it = 0; it < 8; ++it) {
        float Y[9], Z[9];
#pragma unroll
        for (int p = 0; p < 3; ++p)
#pragma unroll
            for (int q = 0; q < 3; ++q)
                Y[p*3+q] = X[p*3+0]*X[q*3+0] + X[p*3+1]*X[q*3+1] + X[p*3+2]*X[q*3+2];
        mm3(Y, X, Z);
#pragma unroll
        for (int m = 0; m < 9; ++m) X[m] = 1.5f*X[m] - 0.5f*Z[m];
    }
}

__global__ void __launch_bounds__(NT, 1)
iekf_kernel(const float* __restrict__ t, const float* __restrict__ u,
            const float* __restrict__ mc, const float* __restrict__ vmes,
            const float* __restrict__ ang0, float* __restrict__ out, int N)
{
    __shared__ SM s;
    const int tid = threadIdx.x;

    // ---------------- prologue ----------------
    float tprev = t[0];
    if (tid == 0) {
        float a0 = ang0[0], a1 = ang0[1], a2 = ang0[2];
        float cr = cosf(a0), sr = sinf(a0), cp = cosf(a1), sp = sinf(a1);
        float cy = cosf(a2), sy = sinf(a2);
        float Rx[9] = {1,0,0, 0,cr,-sr, 0,sr,cr};
        float Ry[9] = {cp,0,sp, 0,1,0, -sp,0,cp};
        float Rz[9] = {cy,-sy,0, sy,cy,0, 0,0,1};
        float T[9], R0[9];
        mm3(Rz, Ry, T); mm3(T, Rx, R0);
#pragma unroll
        for (int m = 0; m < 9; ++m) { s.Rot[m] = R0[m]; s.Rci[m] = (m==0||m==4||m==8) ? 1.f : 0.f; }
#pragma unroll
        for (int q = 0; q < 3; ++q) {
            s.V[q] = vmes[q]; s.Pp[q] = 0.f; s.Bom[q] = 0.f; s.Bac[q] = 0.f; s.Tci[q] = 0.f;
        }
    }
    for (int k = tid; k < 441; k += NT) {
        int i = k / 21, j = k - i*21;
        float pv = 0.f;
        if (i == j) {
            if (i < 2) pv = 0.001f;
            else if (i >= 3 && i < 5) pv = 0.1f;
            else if (i >= 9 && i < 12) pv = 0.006f;
            else if (i >= 12 && i < 15) pv = 0.004f;
            else if (i >= 15 && i < 18) pv = 1e-6f;
            else if (i >= 18) pv = 0.005f;
        }
        s.P[k] = pv;
    }
    if (tid < 9 && N > 1) {
        float v;
        if (tid == 0) v = t[1];
        else if (tid < 7) v = u[6 + (tid-1)];
        else v = mc[2 + (tid-7)];
        s.in[1][tid] = v;
    }
    __syncthreads();

    // ---------------- main loop ----------------
    for (int i = 1; i < N; ++i) {
        const int cur = i & 1;
        const int nxt = cur ^ 1;

        // ===== Phase A =====
        float tc = s.in[cur][0];
        float dt = tc - tprev;
        tprev = tc;
        float dt2 = dt * dt;

        // write outputs of step i-1 (state bufs hold post-(i-1) values)
        {
            int j = i - 1;
            if (tid < 9)       out[j*9 + tid]              = s.Rot[tid];
            else if (tid < 12) out[9*N  + j*3 + (tid-9)]   = s.V[tid-9];
            else if (tid < 15) out[12*N + j*3 + (tid-12)]  = s.Pp[tid-12];
            else if (tid < 18) out[15*N + j*3 + (tid-15)]  = s.Bom[tid-15];
            else if (tid < 21) out[18*N + j*3 + (tid-18)]  = s.Bac[tid-18];
            else if (tid < 30) out[21*N + j*9 + (tid-21)]  = s.Rci[tid-21];
            else if (tid < 33) out[30*N + j*3 + (tid-30)]  = s.Tci[tid-30];
        }
        // prefetch inputs for step i+1 (STS in phase B)
        float pf = 0.f;
        if (tid < 9) {
            int nx = i + 1;
            if (nx < N) {
                if (tid == 0) pf = t[nx];
                else if (tid < 7) pf = u[nx*6 + (tid-1)];
                else pf = mc[nx*2 + (tid-7)];
            }
        }
        // compact F (x dt): rows 0..8, cols {0..5, 9..14}
        for (int k = tid; k < 108; k += NT) {
            int r = k / 12, cc = k - r*12;
            int br = r / 3, rr = r - br*3, bc = cc / 3, j = cc - bc*3;
            float v = 0.f;
            if (br == 0) {
                if (bc == 2) v = -dt * s.Rot[rr*3+j];
            } else if (br == 1) {
                if (bc == 0) v = dt * SG(rr, j);
                else if (bc == 2) v = -dt * skewrowdot(s.V, s.Rot, rr, j);
                else if (bc == 3) v = -dt * s.Rot[rr*3+j];
            } else {
                if (bc == 1) v = (rr == j) ? dt : 0.f;
                else if (bc == 2) v = -dt * skewrowdot(s.Pp, s.Rot, rr, j);
            }
            s.Fc[k] = v;
        }
        // A = P + G Q G^T
        for (int k = tid; k < 441; k += NT) {
            int ii = k / 21, jj = k - ii*21;
            float gq = 0.f;
            if (ii < 3 && jj < 3) {
                float m = s.Rot[ii*3+0]*s.Rot[jj*3+0] + s.Rot[ii*3+1]*s.Rot[jj*3+1] + s.Rot[ii*3+2]*s.Rot[jj*3+2];
                gq = 0.001f * dt2 * m;
            } else if (ii >= 3 && ii < 6 && jj >= 3 && jj < 6) {
                int i3 = ii - 3, j3 = jj - 3;
                float m = s.Rot[i3*3+0]*s.Rot[j3*3+0] + s.Rot[i3*3+1]*s.Rot[j3*3+1] + s.Rot[i3*3+2]*s.Rot[j3*3+2];
                gq = 0.01f * dt2 * m;
            } else if (ii == jj) {
                if (ii >= 9 && ii < 12)       gq = 6e-9f * dt2;
                else if (ii >= 12 && ii < 15) gq = 2e-4f * dt2;
                else if (ii >= 15)            gq = 1e-9f * dt2;
            }
            s.A[k] = s.P[k] + gq;
        }
        // state propagation (serial, hidden behind loop work of others)
        if (tid == NT-1) {
            float w[3]  = {s.in[cur][1] - s.Bom[0], s.in[cur][2] - s.Bom[1], s.in[cur][3] - s.Bom[2]};
            float da[3] = {s.in[cur][4] - s.Bac[0], s.in[cur][5] - s.Bac[1], s.in[cur][6] - s.Bac[2]};
            float phi[3] = {w[0]*dt, w[1]*dt, w[2]*dt};
            float E[9]; so3exp_f(phi, E);
            float Rn[9]; mm3(s.Rot, E, Rn);
            float acc[3];
#pragma unroll
            for (int q = 0; q < 3; ++q)
                acc[q] = s.Rot[q*3+0]*da[0] + s.Rot[q*3+1]*da[1] + s.Rot[q*3+2]*da[2] + ((q == 2) ? GZ : 0.f);
#pragma unroll
            for (int m = 0; m < 9; ++m) s.Rotn[m] = Rn[m];
#pragma unroll
            for (int q = 0; q < 3; ++q) {
                s.Vn[q]  = s.V[q] + acc[q]*dt;
                s.Pn3[q] = s.Pp[q] + s.V[q]*dt + 0.5f*acc[q]*dt2;
                s.Om[q]  = w[q];
            }
        }
        __syncthreads();

        // ===== Phase B: L = F + F^2/2 + F^3/6 ; H ; r ; store prefetch =====
        if (tid < 9) s.in[nxt][tid] = pf;
        for (int k = tid; k < 108; k += NT) {
            int r = k / 12, cc = k - r*12;
            float f2row[6];
#pragma unroll
            for (int kk = 0; kk < 6; ++kk) {
                float a = 0.f;
#pragma unroll
                for (int m = 0; m < 6; ++m) a += s.Fc[r*12+m] * s.Fc[m*12+kk];
                f2row[kk] = a;
            }
            float f2rc = 0.f, f3rc = 0.f;
#pragma unroll
            for (int m = 0; m < 6; ++m) f2rc += s.Fc[r*12+m] * s.Fc[m*12+cc];
#pragma unroll
            for (int kk = 0; kk < 6; ++kk) f3rc += f2row[kk] * s.Fc[kk*12+cc];
            s.L[k] = s.Fc[k] + 0.5f*f2rc + f3rc*(1.f/6.f);
        }
        if (tid >= 128 && tid < 153) {
            int k = tid - 128;
            float vi[3];
#pragma unroll
            for (int q = 0; q < 3; ++q)
                vi[q] = s.Rotn[0*3+q]*s.Vn[0] + s.Rotn[1*3+q]*s.Vn[1] + s.Rotn[2*3+q]*s.Vn[2];
            if (k < 24) {
                int a = k / 12, cc = k - a*12, b = cc / 3, j = cc - b*3;
                float hv;
                if (b == 0) {
                    hv = s.Rotn[j*3+0]*s.Rci[0*3+a+1] + s.Rotn[j*3+1]*s.Rci[1*3+a+1] + s.Rotn[j*3+2]*s.Rci[2*3+a+1];
                } else if (b == 1) {
                    hv = skew_elem(s.Tci, a+1, j);
                } else if (b == 2) {
                    hv = s.Rci[0*3+a+1]*skew_elem(vi,0,j) + s.Rci[1*3+a+1]*skew_elem(vi,1,j) + s.Rci[2*3+a+1]*skew_elem(vi,2,j);
                } else {
                    hv = -skew_elem(s.Om, a+1, j);
                }
                s.H[a*12+cc] = hv;
            } else {
                float cx[3] = { s.Tci[1]*s.Om[2] - s.Tci[2]*s.Om[1],
                                s.Tci[2]*s.Om[0] - s.Tci[0]*s.Om[2],
                                s.Tci[0]*s.Om[1] - s.Tci[1]*s.Om[0] };
#pragma unroll
                for (int p = 1; p < 3; ++p) {
                    float vb = s.Rci[0*3+p]*vi[0] + s.Rci[1*3+p]*vi[1] + s.Rci[2*3+p]*vi[2] + cx[p];
                    s.r2[p-1] = -vb;
                }
                s.Rm2[0] = s.in[cur][7]; s.Rm2[1] = s.in[cur][8];
            }
        }
        __syncthreads();

        // ===== Phase C: T9 = rows 0..8 of (A + L@A) =====
        for (int k = tid; k < 189; k += NT) {
            int r = k / 21, c = k - r*21;
            float a = s.A[k];
#pragma unroll
            for (int cc = 0; cc < 12; ++cc)
                a += s.L[r*12+cc] * s.A[cLCOL[cc]*21 + c];
            s.T9[k] = a;
        }
        __syncthreads();

        // ===== Phase D: Pn = B + B@L^T (cols 0..8 only change) =====
        for (int k = tid; k < 441; k += NT) {
            int r = k / 21, c = k - r*21;
            float b = (r < 9) ? s.T9[k] : s.A[k];
            if (c < 9) {
#pragma unroll
                for (int cc = 0; cc < 12; ++cc) {
                    int col = cLCOL[cc];
                    float brc = (r < 9) ? s.T9[r*21+col] : s.A[r*21+col];
                    b += brc * s.L[c*12+cc];
                }
            }
            s.Pn[k] = b;
        }
        __syncthreads();

        // ===== Phase E: HP = H@Pn ; S = H Pn H^T + Rm =====
        for (int k = tid; k < 42; k += NT) {
            int a = k / 21, c = k - a*21;
            float acc = 0.f;
#pragma unroll
            for (int l = 0; l < 12; ++l) acc += s.H[a*12+l] * s.Pn[cHCOL[l]*21 + c];
            s.HP[k] = acc;
        }
        if (tid >= 64 && tid < 68) {
            int a = (tid - 64) >> 1, b = (tid - 64) & 1;
            float acc = 0.f;
#pragma unroll
            for (int kk = 0; kk < 12; ++kk) {
                float inner = 0.f;
#pragma unroll
                for (int l = 0; l < 12; ++l) inner += s.Pn[cHCOL[kk]*21 + cHCOL[l]] * s.H[b*12+l];
                acc += s.H[a*12+kk] * inner;
            }
            if (a == b) acc += s.Rm2[a];
            s.S[a*2+b] = acc;
        }
        __syncthreads();

        // ===== Phase F: K = (S^{-1} HP)^T ; KS = K@S ; dx = K@r =====
        if (tid < 21) {
            float s00 = s.S[0], s01 = s.S[1], s10 = s.S[2], s11 = s.S[3];
            float id = 1.f / (s00*s11 - s01*s10);
            float h0 = s.HP[0*21+tid], h1 = s.HP[1*21+tid];
            float k0 = id * ( s11*h0 - s01*h1);
            float k1 = id * (-s10*h0 + s00*h1);
            s.K[tid*2+0] = k0; s.K[tid*2+1] = k1;
            s.KS[tid*2+0] = k0*s00 + k1*s10;
            s.KS[tid*2+1] = k0*s01 + k1*s11;
            s.dx[tid] = k0*s.r2[0] + k1*s.r2[1];
        }
        __syncthreads();

        // ===== Phase G: Joseph update into P ; state update =====
        for (int k = tid; k < 441; k += NT) {
            int ii = k / 21, jj = k - ii*21;
            float v = 0.5f * (s.Pn[ii*21+jj] + s.Pn[jj*21+ii])
                - s.K[ii*2+0]*s.HP[0*21+jj] - s.K[ii*2+1]*s.HP[1*21+jj]
                - s.HP[0*21+ii]*s.K[jj*2+0] - s.HP[1*21+ii]*s.K[jj*2+1]
                + s.KS[ii*2+0]*s.K[jj*2+0] + s.KS[ii*2+1]*s.K[jj*2+1];
            s.P[k] = v;
        }
        if (tid == NT-2) {
            float xi[9];
#pragma unroll
            for (int m = 0; m < 9; ++m) xi[m] = s.dx[m];
            float dR[9], x0[3], x1[3];
            sen3exp_f(xi, dR, x0, x1);
            float Ru[9]; mm3(dR, s.Rotn, Ru);
            float vu[3], pu[3];
#pragma unroll
            for (int q = 0; q < 3; ++q) {
                vu[q] = dR[q*3+0]*s.Vn[0]  + dR[q*3+1]*s.Vn[1]  + dR[q*3+2]*s.Vn[2]  + x0[q];
                pu[q] = dR[q*3+0]*s.Pn3[0] + dR[q*3+1]*s.Pn3[1] + dR[q*3+2]*s.Pn3[2] + x1[q];
            }
            if (i % 100 == 0) normrot(Ru);
#pragma unroll
            for (int m = 0; m < 9; ++m) s.Rot[m] = Ru[m];
#pragma unroll
            for (int q = 0; q < 3; ++q) { s.V[q] = vu[q]; s.Pp[q] = pu[q]; }
        }
        if (tid == NT-1) {
            float ph[3] = {s.dx[15], s.dx[16], s.dx[17]};
            float E[9]; so3exp_f(ph, E);
            float Rc[9]; mm3(E, s.Rci, Rc);
            if (i % 1000 == 0) normrot(Rc);
#pragma unroll
            for (int m = 0; m < 9; ++m) s.Rci[m] = Rc[m];
#pragma unroll
            for (int q = 0; q < 3; ++q) {
                s.Bom[q] += s.dx[9+q];
                s.Bac[q] += s.dx[12+q];
                s.Tci[q] += s.dx[18+q];
            }
        }
        __syncthreads();
    }

    // ---------------- epilogue: write final step ----------------
    {
        int j = N - 1;
        if (tid < 9)       out[j*9 + tid]              = s.Rot[tid];
        else if (tid < 12) out[9*N  + j*3 + (tid-9)]   = s.V[tid-9];
        else if (tid < 15) out[12*N + j*3 + (tid-12)]  = s.Pp[tid-12];
        else if (tid < 18) out[15*N + j*3 + (tid-15)]  = s.Bom[tid-15];
        else if (tid < 21) out[18*N + j*3 + (tid-18)]  = s.Bac[tid-18];
        else if (tid < 30) out[21*N + j*9 + (tid-21)]  = s.Rci[tid-21];
        else if (tid < 33) out[30*N + j*3 + (tid-30)]  = s.Tci[tid-30];
    }
}

extern "C" void kernel_launch(void* const* d_in, const int* in_sizes, int n_in,
                              void* d_out, int out_size) {
    const float* t    = (const float*)d_in[0];
    const float* u    = (const float*)d_in[1];
    const float* mcov = (const float*)d_in[2];
    const float* vmes = (const float*)d_in[3];
    const float* ang0 = (const float*)d_in[5];
    float* out = (float*)d_out;
    int N = in_sizes[0];
    iekf_kernel<<<1, NT>>>(t, u, mcov, vmes, ang0, out, N);
}